// round 14
// baseline (speedup 1.0000x reference)
#include <cuda_runtime.h>
#include <cstdint>

#define F_FRAMES 64
#define N_PTS    4096
#define M_BOX    128
#define BLOCKS_PER_FRAME 16
#define PTS_PER_BLOCK    (N_PTS / BLOCKS_PER_FRAME)   // 256
#define THREADS  256
#define GRID     (F_FRAMES * BLOCKS_PER_FRAME)        // 1024

// table: float4 per center = (-2cx, -2cy, cx^2+cy^2, 0); padded to multiple of 8
#define TAB_SLOTS 136

__device__ float    g_sum[F_FRAMES];
__device__ int      g_cnt[F_FRAMES];

__global__ __launch_bounds__(THREADS)
void calib_loss_kernel(const float* __restrict__ points,
                       const float* __restrict__ bboxes,
                       const int*   __restrict__ inL,
                       const int*   __restrict__ inR,
                       const float* __restrict__ quat,
                       const float* __restrict__ trans,
                       const float* __restrict__ K)
{
    __shared__ float4 sTL[TAB_SLOTS];
    __shared__ float4 sTR[TAB_SLOTS];
    __shared__ int    nCL, nCR;
    __shared__ float  warpSum[THREADS / 32];
    __shared__ int    warpCnt[THREADS / 32];

    const int tid  = threadIdx.x;
    const int lane = tid & 31;
    const int wid  = tid >> 5;
    const int f    = blockIdx.x / BLOCKS_PER_FRAME;
    const int blk  = blockIdx.x % BLOCKS_PER_FRAME;

    if (tid == 0) { nCL = 0; nCR = 0; }
    // sentinel prefill: h = 3e38 never wins the min
    if (tid < TAB_SLOTS) {
        float4 s = make_float4(0.f, 0.f, 3e38f, 0.f);
        sTL[tid] = s;
        sTR[tid] = s;
    }
    __syncthreads();

    // ---- Compact valid centers into expanded-square tables ----
    if (tid < M_BOX) {
        int j = tid;
        const float* bb = bboxes + ((size_t)f * M_BOX + j) * 4;
        float cx = bb[0], cy = bb[1];
        float4 ent = make_float4(-2.f * cx, -2.f * cy, fmaf(cx, cx, cy * cy), 0.f);
        bool fl = inL[f * M_BOX + j] > 0;
        bool fr = inR[f * M_BOX + j] > 0;
        unsigned ml = __ballot_sync(0xffffffffu, fl);
        if (ml) {
            int leader = __ffs(ml) - 1;
            int base = 0;
            if (lane == leader) base = atomicAdd(&nCL, __popc(ml));
            base = __shfl_sync(0xffffffffu, base, leader);
            if (fl) sTL[base + __popc(ml & ((1u << lane) - 1u))] = ent;
        }
        unsigned mr = __ballot_sync(0xffffffffu, fr);
        if (mr) {
            int leader = __ffs(mr) - 1;
            int base = 0;
            if (lane == leader) base = atomicAdd(&nCR, __popc(mr));
            base = __shfl_sync(0xffffffffu, base, leader);
            if (fr) sTR[base + __popc(mr & ((1u << lane) - 1u))] = ent;
        }
    }

    // ---- Fold projection: A = K@R (normalized quaternion), b = K@t ----
    const float oqx = quat[0], oqy = quat[1], oqz = quat[2], oqw = quat[3];
    float qn = rsqrtf(oqx*oqx + oqy*oqy + oqz*oqz + oqw*oqw);
    float qx = oqx*qn, qy = oqy*qn, qz = oqz*qn, qw = oqw*qn;
    float R00 = 1.f - 2.f*(qy*qy + qz*qz), R01 = 2.f*(qx*qy - qz*qw), R02 = 2.f*(qx*qz + qy*qw);
    float R10 = 2.f*(qx*qy + qz*qw), R11 = 1.f - 2.f*(qx*qx + qz*qz), R12 = 2.f*(qy*qz - qx*qw);
    float R20 = 2.f*(qx*qz - qy*qw), R21 = 2.f*(qy*qz + qx*qw), R22 = 1.f - 2.f*(qx*qx + qy*qy);
    const float tx = trans[0], ty = trans[1], tz = trans[2];
    const float k00 = K[0], k01 = K[1], k02 = K[2];
    const float k10 = K[3], k11 = K[4], k12 = K[5];
    const float k20 = K[6], k21 = K[7], k22 = K[8];
    float a00 = k00*R00 + k01*R10 + k02*R20, a01 = k00*R01 + k01*R11 + k02*R21, a02 = k00*R02 + k01*R12 + k02*R22;
    float a10 = k10*R00 + k11*R10 + k12*R20, a11 = k10*R01 + k11*R11 + k12*R21, a12 = k10*R02 + k11*R12 + k12*R22;
    float a20 = k20*R00 + k21*R10 + k22*R20, a21 = k20*R01 + k21*R11 + k22*R21, a22 = k20*R02 + k21*R12 + k22*R22;
    float b0 = k00*tx + k01*ty + k02*tz;
    float b1 = k10*tx + k11*ty + k12*tz;
    float b2 = k20*tx + k21*ty + k22*tz;

    __syncthreads();

    const int cntL = nCL, cntR = nCR;
    // ONE blockwide loop bound for both tables: multiple of 8 centers
    const int maxC = (cntL > cntR) ? cntL : cntR;
    const int nC   = (maxC + 7) & ~7;

    // ---- One point per thread: expanded-square scan (4 slots/iter) ----
    float accS = 0.f;
    int   accC = 0;
    {
        int n = blk * PTS_PER_BLOCK + tid;
        const float* pt = points + ((size_t)f * N_PTS + n) * 5;
        float x  = pt[0], y = pt[1], z = pt[2], vy = pt[4];

        const float4* cp = (vy > 0.f) ? sTL : sTR;
        const bool pv = ((vy > 0.f) && (cntL > 0)) || ((vy < 0.f) && (cntR > 0));

        float w  = fmaf(a20, x, fmaf(a21, y, fmaf(a22, z, b2)));
        float iw = __fdividef(1.f, w);
        float u  = fmaf(a00, x, fmaf(a01, y, fmaf(a02, z, b0))) * iw;
        float v  = fmaf(a10, x, fmaf(a11, y, fmaf(a12, z, b1))) * iw;
        float u2v2 = fmaf(u, u, v * v);

        float m0 = 3e38f, m1 = 3e38f, m2 = 3e38f, m3 = 3e38f;
        for (int k = 0; k < nC; k += 4) {
            float4 c0 = cp[k + 0];
            float4 c1 = cp[k + 1];
            float4 c2 = cp[k + 2];
            float4 c3 = cp[k + 3];
            // score = h - 2u*cx - 2v*cy  (dist^2 = u2v2 + score)
            m0 = fminf(m0, fmaf(u, c0.x, fmaf(v, c0.y, c0.z)));
            m1 = fminf(m1, fmaf(u, c1.x, fmaf(v, c1.y, c1.z)));
            m2 = fminf(m2, fmaf(u, c2.x, fmaf(v, c2.y, c2.z)));
            m3 = fminf(m3, fmaf(u, c3.x, fmaf(v, c3.y, c3.z)));
        }
        float smin  = fminf(fminf(m0, m1), fminf(m2, m3));
        float dmin2 = fmaxf(u2v2 + smin, 0.f);
        float ds = sqrtf(dmin2);
        float h  = (ds <= 50.f) ? (0.5f * dmin2) : (50.f * (ds - 25.f));
        accS = pv ? h : 0.f;
        accC = pv ? 1 : 0;
    }

    // ---- Block reduction ----
    #pragma unroll
    for (int o = 16; o > 0; o >>= 1) {
        accS += __shfl_down_sync(0xffffffffu, accS, o);
        accC += __shfl_down_sync(0xffffffffu, accC, o);
    }
    if (lane == 0) { warpSum[wid] = accS; warpCnt[wid] = accC; }
    __syncthreads();

    if (wid == 0) {
        float s = (lane < THREADS / 32) ? warpSum[lane] : 0.f;
        int   c = (lane < THREADS / 32) ? warpCnt[lane] : 0;
        #pragma unroll
        for (int o = 4; o > 0; o >>= 1) {
            s += __shfl_down_sync(0xffffffffu, s, o);
            c += __shfl_down_sync(0xffffffffu, c, o);
        }
        if (lane == 0 && c > 0) {
            atomicAdd(&g_sum[f], s);
            atomicAdd(&g_cnt[f], c);
        }
    }
}

// Tiny finish kernel: one frame per thread, parallel loads, then reduce.
// Also resets g_sum/g_cnt so every graph replay starts from zero.
__global__ __launch_bounds__(F_FRAMES)
void finish_kernel(const float* __restrict__ quat,
                   const float* __restrict__ trans,
                   float*       __restrict__ out)
{
    __shared__ float sS[2];
    __shared__ int   sC[2];
    const int t    = threadIdx.x;          // 0..63
    const int lane = t & 31;
    const int wid  = t >> 5;

    float ss = g_sum[t];
    int   cc = g_cnt[t];
    g_sum[t] = 0.f;
    g_cnt[t] = 0;

    float fl = (cc > 0) ? (ss / (float)cc) : 0.f;
    int   nz = (cc > 0) ? 1 : 0;

    #pragma unroll
    for (int o = 16; o > 0; o >>= 1) {
        fl += __shfl_down_sync(0xffffffffu, fl, o);
        nz += __shfl_down_sync(0xffffffffu, nz, o);
    }
    if (lane == 0) { sS[wid] = fl; sC[wid] = nz; }
    __syncthreads();

    if (t == 0) {
        float total = sS[0] + sS[1];
        int   nf    = sC[0] + sC[1];
        float avg = (nf > 0) ? (total / (float)nf) : 0.f;
        float oqx = quat[0], oqy = quat[1], oqz = quat[2], oqw = quat[3];
        float tx = trans[0], ty = trans[1], tz = trans[2];
        float nrm = sqrtf(oqx*oqx + oqy*oqy + oqz*oqz + oqw*oqw);
        float dq  = 1.f - nrm;
        float reg = 0.01f * (tx*tx + ty*ty + tz*tz + dq*dq);
        out[0] = avg + reg;
    }
}

extern "C" void kernel_launch(void* const* d_in, const int* in_sizes, int n_in,
                              void* d_out, int out_size)
{
    const float* points = (const float*)d_in[0];
    const float* bboxes = (const float*)d_in[1];
    const int*   inL    = (const int*)  d_in[2];
    const int*   inR    = (const int*)  d_in[3];
    const float* quat   = (const float*)d_in[4];
    const float* trans  = (const float*)d_in[5];
    const float* K      = (const float*)d_in[6];
    float*       out    = (float*)d_out;
    (void)in_sizes; (void)n_in; (void)out_size;

    calib_loss_kernel<<<GRID, THREADS>>>(points, bboxes, inL, inR, quat, trans, K);
    finish_kernel<<<1, F_FRAMES>>>(quat, trans, out);
}

// round 15
// speedup vs baseline: 1.9543x; 1.9543x over previous
#include <cuda_runtime.h>
#include <cstdint>

#define F_FRAMES 64
#define N_PTS    4096
#define M_BOX    128
#define THREADS  256
#define SUBS     8
#define PTS_PER_SUB (N_PTS / SUBS)      // 512 points per (parity,sub) block range
#define GRID     (F_FRAMES * 2 * SUBS)  // 1024 blocks

// pair-interleaved table: float4 = (ncx0, ncx1, ncy0, ncy1); 66 pairs = 132 center slots
#define TAB_PAIRS 66

__device__ float    g_sum[F_FRAMES];
__device__ int      g_cnt[F_FRAMES];

__device__ __forceinline__ uint64_t pack2(float lo, float hi) {
    uint64_t r; asm("mov.b64 %0, {%1, %2};" : "=l"(r) : "f"(lo), "f"(hi)); return r;
}
__device__ __forceinline__ void unpack2(float& lo, float& hi, uint64_t v) {
    asm("mov.b64 {%0, %1}, %2;" : "=f"(lo), "=f"(hi) : "l"(v));
}
__device__ __forceinline__ uint64_t add2(uint64_t a, uint64_t b) {
    uint64_t r; asm("add.rn.f32x2 %0, %1, %2;" : "=l"(r) : "l"(a), "l"(b)); return r;
}
__device__ __forceinline__ uint64_t mul2(uint64_t a, uint64_t b) {
    uint64_t r; asm("mul.rn.f32x2 %0, %1, %2;" : "=l"(r) : "l"(a), "l"(b)); return r;
}
__device__ __forceinline__ uint64_t fma2(uint64_t a, uint64_t b, uint64_t c) {
    uint64_t r; asm("fma.rn.f32x2 %0, %1, %2, %3;" : "=l"(r) : "l"(a), "l"(b), "l"(c)); return r;
}

__global__ __launch_bounds__(THREADS)
void calib_loss_kernel(const float* __restrict__ points,
                       const float* __restrict__ bboxes,
                       const int*   __restrict__ inL,
                       const int*   __restrict__ inR,
                       const float* __restrict__ quat,
                       const float* __restrict__ trans,
                       const float* __restrict__ K)
{
    __shared__ float4 sTab[TAB_PAIRS];
    __shared__ float2 sPts[PTS_PER_SUB];
    __shared__ int    nC, nP;
    __shared__ float  warpSum[THREADS / 32];
    __shared__ int    warpCnt[THREADS / 32];

    const int tid    = threadIdx.x;
    const int lane   = tid & 31;
    const int wid    = tid >> 5;
    const int bx     = blockIdx.x;
    const int f      = bx >> 4;            // 16 blocks per frame
    const int r      = bx & 15;
    const int parity = r >> 3;             // 0 = left (vy>0), 1 = right (vy<0)
    const int sub    = r & 7;

    if (tid == 0) { nC = 0; nP = 0; }
    // sentinel prefill (negated-center convention: -(-1e18) never wins a min)
    if (tid < TAB_PAIRS) {
        sTab[tid] = make_float4(-1e18f, -1e18f, -1e18f, -1e18f);
    }
    __syncthreads();

    // ---- Build the ONE table this block needs (parity-selected flags) ----
    if (tid < M_BOX) {
        int j = tid;
        const float* bb = bboxes + ((size_t)f * M_BOX + j) * 4;
        float ncx = -bb[0], ncy = -bb[1];
        const int* flags = parity ? inR : inL;
        bool fl = flags[f * M_BOX + j] > 0;
        unsigned ml = __ballot_sync(0xffffffffu, fl);
        if (ml) {
            int leader = __ffs(ml) - 1;
            int base = 0;
            if (lane == leader) base = atomicAdd(&nC, __popc(ml));
            base = __shfl_sync(0xffffffffu, base, leader);
            if (fl) {
                int i = base + __popc(ml & ((1u << lane) - 1u));
                float* e = (float*)&sTab[i >> 1];
                e[i & 1] = ncx; e[2 + (i & 1)] = ncy;
            }
        }
    }

    // ---- Fold projection: A = K@R (normalized quaternion), b = K@t ----
    const float oqx = quat[0], oqy = quat[1], oqz = quat[2], oqw = quat[3];
    float qn = rsqrtf(oqx*oqx + oqy*oqy + oqz*oqz + oqw*oqw);
    float qx = oqx*qn, qy = oqy*qn, qz = oqz*qn, qw = oqw*qn;
    float R00 = 1.f - 2.f*(qy*qy + qz*qz), R01 = 2.f*(qx*qy - qz*qw), R02 = 2.f*(qx*qz + qy*qw);
    float R10 = 2.f*(qx*qy + qz*qw), R11 = 1.f - 2.f*(qx*qx + qz*qz), R12 = 2.f*(qy*qz - qx*qw);
    float R20 = 2.f*(qx*qz - qy*qw), R21 = 2.f*(qy*qz + qx*qw), R22 = 1.f - 2.f*(qx*qx + qy*qy);
    const float tx = trans[0], ty = trans[1], tz = trans[2];
    const float k00 = K[0], k01 = K[1], k02 = K[2];
    const float k10 = K[3], k11 = K[4], k12 = K[5];
    const float k20 = K[6], k21 = K[7], k22 = K[8];
    float a00 = k00*R00 + k01*R10 + k02*R20, a01 = k00*R01 + k01*R11 + k02*R21, a02 = k00*R02 + k01*R12 + k02*R22;
    float a10 = k10*R00 + k11*R10 + k12*R20, a11 = k10*R01 + k11*R11 + k12*R21, a12 = k10*R02 + k11*R12 + k12*R22;
    float a20 = k20*R00 + k21*R10 + k22*R20, a21 = k20*R01 + k21*R11 + k22*R21, a22 = k20*R02 + k21*R12 + k22*R22;
    float b0 = k00*tx + k01*ty + k02*tz;
    float b1 = k10*tx + k11*ty + k12*tz;
    float b2 = k20*tx + k21*ty + k22*tz;

    __syncthreads();

    // ---- Project this block's 512-point range; keep matching-sign points ----
    #pragma unroll
    for (int k = 0; k < PTS_PER_SUB / THREADS; ++k) {
        int n = sub * PTS_PER_SUB + k * THREADS + tid;
        const float* pt = points + ((size_t)f * N_PTS + n) * 5;
        float x = pt[0], y = pt[1], z = pt[2], vy = pt[4];

        bool keep = parity ? (vy < 0.f) : (vy > 0.f);

        float w  = fmaf(a20, x, fmaf(a21, y, fmaf(a22, z, b2)));
        float iw = __fdividef(1.f, w);
        float u  = fmaf(a00, x, fmaf(a01, y, fmaf(a02, z, b0))) * iw;
        float v  = fmaf(a10, x, fmaf(a11, y, fmaf(a12, z, b1))) * iw;

        unsigned mk = __ballot_sync(0xffffffffu, keep);
        if (mk) {
            int leader = __ffs(mk) - 1;
            int base = 0;
            if (lane == leader) base = atomicAdd(&nP, __popc(mk));
            base = __shfl_sync(0xffffffffu, base, leader);
            if (keep) sPts[base + __popc(mk & ((1u << lane) - 1u))] = make_float2(u, v);
        }
    }
    __syncthreads();

    const int cnt = nC;
    const int np  = nP;
    const int nPairs = ((cnt + 3) & ~3) >> 1;   // multiple of 2 pairs

    // ---- Scan: single uniform table, R10 packed loop verbatim ----
    float accS = 0.f;
    int   accC = 0;
    if (cnt > 0) {
        for (int i = tid; i < np; i += THREADS) {
            float2 p = sPts[i];
            uint64_t UU = pack2(p.x, p.x);
            uint64_t VV = pack2(p.y, p.y);
            const ulonglong2* cp = (const ulonglong2*)sTab;

            float m0 = 3.9e37f, m1 = 3.9e37f, m2 = 3.9e37f, m3 = 3.9e37f;
            #pragma unroll 2
            for (int k = 0; k < nPairs; k += 2) {
                ulonglong2 t0 = cp[k];
                ulonglong2 t1 = cp[k + 1];
                uint64_t dx0 = add2(UU, t0.x);   // u - cx (centers stored negated)
                uint64_t dy0 = add2(VV, t0.y);
                uint64_t dx1 = add2(UU, t1.x);
                uint64_t dy1 = add2(VV, t1.y);
                uint64_t dd0 = fma2(dx0, dx0, mul2(dy0, dy0));
                uint64_t dd1 = fma2(dx1, dx1, mul2(dy1, dy1));
                float a, b, c, d;
                unpack2(a, b, dd0);
                unpack2(c, d, dd1);
                m0 = fminf(m0, a); m1 = fminf(m1, b);
                m2 = fminf(m2, c); m3 = fminf(m3, d);
            }
            float dmin2 = fminf(fminf(m0, m1), fminf(m2, m3));
            float ds = sqrtf(dmin2);
            accS += (ds <= 50.f) ? (0.5f * dmin2) : (50.f * (ds - 25.f));
            accC += 1;
        }
    }

    // ---- Block reduction ----
    #pragma unroll
    for (int o = 16; o > 0; o >>= 1) {
        accS += __shfl_down_sync(0xffffffffu, accS, o);
        accC += __shfl_down_sync(0xffffffffu, accC, o);
    }
    if (lane == 0) { warpSum[wid] = accS; warpCnt[wid] = accC; }
    __syncthreads();

    if (wid == 0) {
        float s = (lane < THREADS / 32) ? warpSum[lane] : 0.f;
        int   c = (lane < THREADS / 32) ? warpCnt[lane] : 0;
        #pragma unroll
        for (int o = 4; o > 0; o >>= 1) {
            s += __shfl_down_sync(0xffffffffu, s, o);
            c += __shfl_down_sync(0xffffffffu, c, o);
        }
        if (lane == 0 && c > 0) {
            atomicAdd(&g_sum[f], s);
            atomicAdd(&g_cnt[f], c);
        }
    }
}

// Tiny finish kernel: one frame per thread, parallel loads, then reduce.
// Also resets g_sum/g_cnt so every graph replay starts from zero.
__global__ __launch_bounds__(F_FRAMES)
void finish_kernel(const float* __restrict__ quat,
                   const float* __restrict__ trans,
                   float*       __restrict__ out)
{
    __shared__ float sS[2];
    __shared__ int   sC[2];
    const int t    = threadIdx.x;          // 0..63
    const int lane = t & 31;
    const int wid  = t >> 5;

    float ss = g_sum[t];
    int   cc = g_cnt[t];
    g_sum[t] = 0.f;
    g_cnt[t] = 0;

    float fl = (cc > 0) ? (ss / (float)cc) : 0.f;
    int   nz = (cc > 0) ? 1 : 0;

    #pragma unroll
    for (int o = 16; o > 0; o >>= 1) {
        fl += __shfl_down_sync(0xffffffffu, fl, o);
        nz += __shfl_down_sync(0xffffffffu, nz, o);
    }
    if (lane == 0) { sS[wid] = fl; sC[wid] = nz; }
    __syncthreads();

    if (t == 0) {
        float total = sS[0] + sS[1];
        int   nf    = sC[0] + sC[1];
        float avg = (nf > 0) ? (total / (float)nf) : 0.f;
        float oqx = quat[0], oqy = quat[1], oqz = quat[2], oqw = quat[3];
        float tx = trans[0], ty = trans[1], tz = trans[2];
        float nrm = sqrtf(oqx*oqx + oqy*oqy + oqz*oqz + oqw*oqw);
        float dq  = 1.f - nrm;
        float reg = 0.01f * (tx*tx + ty*ty + tz*tz + dq*dq);
        out[0] = avg + reg;
    }
}

extern "C" void kernel_launch(void* const* d_in, const int* in_sizes, int n_in,
                              void* d_out, int out_size)
{
    const float* points = (const float*)d_in[0];
    const float* bboxes = (const float*)d_in[1];
    const int*   inL    = (const int*)  d_in[2];
    const int*   inR    = (const int*)  d_in[3];
    const float* quat   = (const float*)d_in[4];
    const float* trans  = (const float*)d_in[5];
    const float* K      = (const float*)d_in[6];
    float*       out    = (float*)d_out;
    (void)in_sizes; (void)n_in; (void)out_size;

    calib_loss_kernel<<<GRID, THREADS>>>(points, bboxes, inL, inR, quat, trans, K);
    finish_kernel<<<1, F_FRAMES>>>(quat, trans, out);
}